// round 4
// baseline (speedup 1.0000x reference)
#include <cuda_runtime.h>
#include <math.h>

// Problem constants
#define N1v 4000
#define N2v 4000
#define GD  8000
#define RD  20000
#define M1v 1200
#define M2v 1200
#define MGv 2400
#define MRv 6000

// ---------------- device scratch (no allocation allowed) ----------------
__device__ int    d_s1[M1v], d_s2[M2v], d_sg[MGv], d_sr[MRv];
__device__ float4 d_q1[M1v], d_q2[M2v], d_pg[MGv], d_pr[MRv];
// 0: loss1 sum, 1: loss2 sum, 2: S (unnormalized trace), 3: ||Pg||^2, 4: ||Pr||^2
__device__ double d_acc[5];

// ---------------- helpers ----------------
__device__ __forceinline__ void softmax3(float a, float b, float c,
                                         float& p0, float& p1, float& p2) {
    float m  = fmaxf(a, fmaxf(b, c));
    float e0 = __expf(a - m), e1 = __expf(b - m), e2 = __expf(c - m);
    float inv = 1.0f / (e0 + e1 + e2);
    p0 = e0 * inv; p1 = e1 * inv; p2 = e2 * inv;
}

// ---------------- zero accumulators ----------------
__global__ void zero_kernel() {
    if (threadIdx.x < 5) d_acc[threadIdx.x] = 0.0;
}

// ---------------- counting sort (single block, smem histogram) ----------------
// Sorting the masks is valid: all sums are permutation-invariant, and every
// per-index quantity (softmax rows, biases) depends only on the mask VALUE.
// Sorted indices make the warp gather pattern quasi-coalesced (mean stride ~3.3).
__global__ void count_sort_kernel(const int* __restrict__ in, int n, int vmax, int which) {
    extern __shared__ int sh[];           // vmax counts
    __shared__ int tsum[1024];
    int* out = (which == 0) ? d_s1 : (which == 1) ? d_s2 : (which == 2) ? d_sg : d_sr;
    const int tid = threadIdx.x, bd = blockDim.x;

    for (int v = tid; v < vmax; v += bd) sh[v] = 0;
    __syncthreads();
    for (int k = tid; k < n; k += bd) atomicAdd(&sh[in[k]], 1);
    __syncthreads();

    const int chunk = (vmax + bd - 1) / bd;
    const int c0 = tid * chunk;
    const int c1 = min(c0 + chunk, vmax);
    int mysum = 0;
    for (int v = c0; v < c1; v++) mysum += sh[v];
    tsum[tid] = mysum;
    __syncthreads();
    // Hillis-Steele inclusive scan over 1024 partials
    for (int off = 1; off < bd; off <<= 1) {
        int v = (tid >= off) ? tsum[tid - off] : 0;
        __syncthreads();
        tsum[tid] += v;
        __syncthreads();
    }
    int run = tsum[tid] - mysum;          // exclusive prefix
    for (int v = c0; v < c1; v++) {
        int c = sh[v];
        for (int t = 0; t < c; t++) out[run + t] = v;
        run += c;
    }
}

// ---------------- prep: softmax tables, Q = P@Ai, biases, norms ----------------
__global__ void prep_kernel(const float* __restrict__ C1, const float* __restrict__ C2,
                            const float* __restrict__ Cg, const float* __restrict__ Cr,
                            const float* __restrict__ Ai, const float* __restrict__ bg,
                            const float* __restrict__ br, const float* __restrict__ b1,
                            const float* __restrict__ b2) {
    const int t = blockIdx.x * blockDim.x + threadIdx.x;
    float ng2 = 0.0f, nr2 = 0.0f;

    if (t < MRv) {
        int v = d_sr[t];
        float p0, p1, p2; softmax3(Cr[3*v], Cr[3*v+1], Cr[3*v+2], p0, p1, p2);
        d_pr[t] = make_float4(p0, p1, p2, br[v]);
        nr2 = p0*p0 + p1*p1 + p2*p2;
    } else if (t < MRv + MGv) {
        int j = t - MRv; int v = d_sg[j];
        float p0, p1, p2; softmax3(Cg[3*v], Cg[3*v+1], Cg[3*v+2], p0, p1, p2);
        d_pg[j] = make_float4(p0, p1, p2, bg[v]);
        ng2 = p0*p0 + p1*p1 + p2*p2;
    } else if (t < MRv + MGv + M1v) {
        int i = t - MRv - MGv; int v = d_s1[i];
        float p0, p1, p2; softmax3(C1[3*v], C1[3*v+1], C1[3*v+2], p0, p1, p2);
        float q0 = p0*Ai[0] + p1*Ai[3] + p2*Ai[6];
        float q1 = p0*Ai[1] + p1*Ai[4] + p2*Ai[7];
        float q2 = p0*Ai[2] + p1*Ai[5] + p2*Ai[8];
        d_q1[i] = make_float4(q0, q1, q2, b1[v]);
    } else if (t < MRv + MGv + M1v + M2v) {
        int i = t - MRv - MGv - M1v; int v = d_s2[i];
        float p0, p1, p2; softmax3(C2[3*v], C2[3*v+1], C2[3*v+2], p0, p1, p2);
        float q0 = p0*Ai[0] + p1*Ai[3] + p2*Ai[6];
        float q1 = p0*Ai[1] + p1*Ai[4] + p2*Ai[7];
        float q2 = p0*Ai[2] + p1*Ai[5] + p2*Ai[8];
        d_q2[i] = make_float4(q0, q1, q2, b2[v]);
    }

    // block-reduce norm contributions -> 2 atomics/block (avoid hot-address atomics)
    __shared__ float rg[256], rr[256];
    const int tid = threadIdx.x;
    rg[tid] = ng2; rr[tid] = nr2;
    __syncthreads();
    for (int s = 128; s > 0; s >>= 1) {
        if (tid < s) { rg[tid] += rg[tid + s]; rr[tid] += rr[tid + s]; }
        __syncthreads();
    }
    if (tid == 0) {
        if (rg[0] != 0.0f) atomicAdd(&d_acc[3], (double)rg[0]);
        if (rr[0] != 0.0f) atomicAdd(&d_acc[4], (double)rr[0]);
    }
}

// ---------------- loss1 / loss2: squared-residual gather-reduce ----------------
// mode 0: X=G, rows=s1/q1, cols=sg/pg, acc[0]
// mode 1: X=R, rows=s2/q2, cols=sr/pr, acc[1]
template <int TI>
__global__ void loss_sq_kernel(const float* __restrict__ X, int ld,
                               int MI, int MJ, int mode) {
    __shared__ float4 sq[TI];
    __shared__ int    soff[TI];
    const int tid = threadIdx.x;
    const int i0  = blockIdx.y * TI;

    if (tid < TI) {
        int i = i0 + tid;
        if (i < MI) {
            if (mode == 0) { sq[tid] = d_q1[i]; soff[tid] = d_s1[i] * ld; }
            else           { sq[tid] = d_q2[i]; soff[tid] = d_s2[i] * ld; }
        }
    }
    __syncthreads();

    const int j = blockIdx.x * blockDim.x + tid;
    float acc = 0.0f;
    if (j < MJ) {
        float4 pj; int col;
        if (mode == 0) { pj = d_pg[j]; col = d_sg[j]; }
        else           { pj = d_pr[j]; col = d_sr[j]; }
        const int ilim = min(TI, MI - i0);
        #pragma unroll 4
        for (int i = 0; i < ilim; i++) {
            float4 qi = sq[i];
            float g = __ldg(X + soff[i] + col);
            float r = g - fmaf(qi.x, pj.x, fmaf(qi.y, pj.y, qi.z * pj.z)) - pj.w - qi.w;
            acc = fmaf(r, r, acc);
        }
    }

    __shared__ float red[256];
    red[tid] = acc;
    __syncthreads();
    for (int s = 128; s > 0; s >>= 1) {
        if (tid < s) red[tid] += red[tid + s];
        __syncthreads();
    }
    if (tid == 0) atomicAdd(&d_acc[mode], (double)red[0]);
}

// ---------------- loss3: S = sum_f sum_i sum_j pg[i,f] * A[sg_i, sr_j] * pr[j,f] ----
template <int TI>
__global__ void loss3_kernel(const float* __restrict__ A) {
    __shared__ float4 spg[TI];
    __shared__ int    soff[TI];
    const int tid = threadIdx.x;
    const int i0  = blockIdx.y * TI;

    if (tid < TI) {
        int i = i0 + tid;
        if (i < MGv) { spg[tid] = d_pg[i]; soff[tid] = d_sg[i] * RD; }
    }
    __syncthreads();

    const int j = blockIdx.x * blockDim.x + tid;
    float contrib = 0.0f;
    if (j < MRv) {
        float4 pj = d_pr[j];
        int col   = d_sr[j];
        float a0 = 0.0f, a1 = 0.0f, a2 = 0.0f;
        const int ilim = min(TI, MGv - i0);
        #pragma unroll 4
        for (int i = 0; i < ilim; i++) {
            float a  = __ldg(A + soff[i] + col);
            float4 g = spg[i];
            a0 = fmaf(a, g.x, a0);
            a1 = fmaf(a, g.y, a1);
            a2 = fmaf(a, g.z, a2);
        }
        contrib = a0 * pj.x + a1 * pj.y + a2 * pj.z;
    }

    __shared__ float red[256];
    red[tid] = contrib;
    __syncthreads();
    for (int s = 128; s > 0; s >>= 1) {
        if (tid < s) red[tid] += red[tid + s];
        __syncthreads();
    }
    if (tid == 0) atomicAdd(&d_acc[2], (double)red[0]);
}

// ---------------- finalize ----------------
__global__ void finalize_kernel(float* __restrict__ out) {
    double l1 = d_acc[0] / (double)((long long)M1v * MGv);
    double l2 = d_acc[1] / (double)((long long)M2v * MRv);
    double l3 = -d_acc[2] / (sqrt(d_acc[3]) * sqrt(d_acc[4]));
    double t1 = 1000.0 * l1;
    double t2 = 1000.0 * l2;
    double t3 = 100.0  * l3;
    out[0] = (float)(t1 + t2 + t3);
    out[1] = (float)t1;
    out[2] = (float)t2;
    out[3] = (float)t3;
    out[4] = 0.0f;   // ALPHA[3] == 0 -> 0 * loss4 == 0 exactly
}

// ---------------- launch ----------------
extern "C" void kernel_launch(void* const* d_in, const int* in_sizes, int n_in,
                              void* d_out, int out_size) {
    const float* G  = (const float*)d_in[0];
    const float* R  = (const float*)d_in[1];
    const float* A  = (const float*)d_in[2];
    const float* C1 = (const float*)d_in[3];
    const float* C2 = (const float*)d_in[4];
    const float* Cg = (const float*)d_in[5];
    const float* Cr = (const float*)d_in[6];
    const float* Ai = (const float*)d_in[7];
    const float* bg = (const float*)d_in[8];
    const float* br = (const float*)d_in[9];
    const float* b1 = (const float*)d_in[10];
    const float* b2 = (const float*)d_in[11];
    const int* m1 = (const int*)d_in[12];
    const int* m2 = (const int*)d_in[13];
    const int* mg = (const int*)d_in[14];
    const int* mr = (const int*)d_in[15];
    float* out = (float*)d_out;

    // largest histogram (R_DIM = 20000 ints = 80 KB) exceeds default 48 KB
    cudaFuncSetAttribute(count_sort_kernel,
                         cudaFuncAttributeMaxDynamicSharedMemorySize,
                         RD * (int)sizeof(int));

    zero_kernel<<<1, 32>>>();

    count_sort_kernel<<<1, 1024, N1v * sizeof(int)>>>(m1, M1v, N1v, 0);
    count_sort_kernel<<<1, 1024, N2v * sizeof(int)>>>(m2, M2v, N2v, 1);
    count_sort_kernel<<<1, 1024, GD  * sizeof(int)>>>(mg, MGv, GD,  2);
    count_sort_kernel<<<1, 1024, RD  * sizeof(int)>>>(mr, MRv, RD,  3);

    {
        int total = MRv + MGv + M1v + M2v;          // 10800
        prep_kernel<<<(total + 255) / 256, 256>>>(C1, C2, Cg, Cr, Ai, bg, br, b1, b2);
    }

    {   // loss1: [1200 x 2400] over G
        dim3 g((MGv + 255) / 256, (M1v + 31) / 32);
        loss_sq_kernel<32><<<g, 256>>>(G, GD, M1v, MGv, 0);
    }
    {   // loss2: [1200 x 6000] over R
        dim3 g((MRv + 255) / 256, (M2v + 63) / 64);
        loss_sq_kernel<64><<<g, 256>>>(R, RD, M2v, MRv, 1);
    }
    {   // loss3: [2400 x 6000] over A (dominant)
        dim3 g((MRv + 255) / 256, (MGv + 63) / 64);
        loss3_kernel<64><<<g, 256>>>(A);
    }

    finalize_kernel<<<1, 1>>>(out);
}

// round 5
// speedup vs baseline: 1.4611x; 1.4611x over previous
#include <cuda_runtime.h>
#include <math.h>

// Problem constants
#define N1v 4000
#define N2v 4000
#define GD  8000
#define RD  20000
#define M1v 1200
#define M2v 1200
#define MGv 2400
#define MRv 6000

// Fused loss-kernel grid segmentation (loss3 first: longest-running blocks launch first)
#define GX3 24          // ceil(MRv/256)
#define GY3 38          // ceil(MGv/64)
#define NB3 (GX3*GY3)   // 912
#define GX2 24          // ceil(MRv/256)
#define GY2 19          // ceil(M2v/64)
#define NB2 (GX2*GY2)   // 456
#define GX1 10          // ceil(MGv/256)
#define GY1 38          // ceil(M1v/32)
#define NB1 (GX1*GY1)   // 380
#define NBT (NB3+NB2+NB1)

// ---------------- device scratch (no allocation allowed) ----------------
// Unique sorted values + multiplicity weights per mask axis
__device__ int    d_s1[M1v], d_s2[M2v], d_sg[MGv], d_sr[MRv];
__device__ float  d_w1[M1v], d_w2[M2v], d_wg[MGv], d_wr[MRv];
__device__ float4 d_q1[M1v], d_q2[M2v], d_pg[MGv], d_pr[MRv];
__device__ int    d_nu[4];      // unique counts: [m1, m2, mg, mr]
// 0: loss1 sum, 1: loss2 sum, 2: S (unnormalized trace), 3: ||Pg||^2, 4: ||Pr||^2
__device__ double d_acc[5];

// ---------------- helpers ----------------
__device__ __forceinline__ void softmax3(float a, float b, float c,
                                         float& p0, float& p1, float& p2) {
    float m  = fmaxf(a, fmaxf(b, c));
    float e0 = __expf(a - m), e1 = __expf(b - m), e2 = __expf(c - m);
    float inv = 1.0f / (e0 + e1 + e2);
    p0 = e0 * inv; p1 = e1 * inv; p2 = e2 * inv;
}

// ---------------- fused counting sort + dedup (4 concurrent blocks) ----------------
// Sorting/dedup is exact: all sums are permutation-invariant and every per-index
// quantity depends only on the mask VALUE; duplicates contribute identical terms,
// captured by multiplicity weights. Sorted unique values also make warp gathers
// quasi-coalesced.
__global__ void sort_kernel(const int* __restrict__ m1, const int* __restrict__ m2,
                            const int* __restrict__ mg, const int* __restrict__ mr) {
    extern __shared__ int sh[];           // per-block histogram (up to RD ints)
    __shared__ int wsum[32];
    const int which = blockIdx.x;
    const int tid = threadIdx.x, bd = blockDim.x;   // bd == 1024
    const int lane = tid & 31, wid = tid >> 5;

    const int* in; int n, vmax; int* outv; float* outw;
    if      (which == 0) { in = m1; n = M1v; vmax = N1v; outv = d_s1; outw = d_w1; }
    else if (which == 1) { in = m2; n = M2v; vmax = N2v; outv = d_s2; outw = d_w2; }
    else if (which == 2) { in = mg; n = MGv; vmax = GD;  outv = d_sg; outw = d_wg; }
    else                 { in = mr; n = MRv; vmax = RD;  outv = d_sr; outw = d_wr; }

    if (which == 0 && tid < 5) d_acc[tid] = 0.0;   // zero accumulators (used by later kernels)

    for (int v = tid; v < vmax; v += bd) sh[v] = 0;
    __syncthreads();
    for (int k = tid; k < n; k += bd) atomicAdd(&sh[in[k]], 1);
    __syncthreads();

    const int chunk = (vmax + bd - 1) / bd;
    const int c0 = min(tid * chunk, vmax);
    const int c1 = min(c0 + chunk, vmax);
    int cnt = 0;                                   // # unique values in my chunk
    for (int v = c0; v < c1; v++) cnt += (sh[v] != 0);

    // exclusive scan of cnt across 1024 threads via warp shuffles
    int incl = cnt;
    #pragma unroll
    for (int off = 1; off < 32; off <<= 1) {
        int t = __shfl_up_sync(0xFFFFFFFFu, incl, off);
        if (lane >= off) incl += t;
    }
    if (lane == 31) wsum[wid] = incl;
    __syncthreads();
    if (wid == 0) {
        int s = wsum[lane];
        #pragma unroll
        for (int off = 1; off < 32; off <<= 1) {
            int t = __shfl_up_sync(0xFFFFFFFFu, s, off);
            if (lane >= off) s += t;
        }
        wsum[lane] = s;
    }
    __syncthreads();
    int excl = incl - cnt + (wid > 0 ? wsum[wid - 1] : 0);

    for (int v = c0; v < c1; v++) {
        int c = sh[v];
        if (c) { outv[excl] = v; outw[excl] = (float)c; excl++; }
    }
    if (tid == bd - 1) d_nu[which] = excl;         // last thread's final excl == total unique
}

// ---------------- prep: softmax tables, Q = P@Ai, biases, weighted norms ----------------
__global__ void prep_kernel(const float* __restrict__ C1, const float* __restrict__ C2,
                            const float* __restrict__ Cg, const float* __restrict__ Cr,
                            const float* __restrict__ Ai, const float* __restrict__ bg,
                            const float* __restrict__ br, const float* __restrict__ b1,
                            const float* __restrict__ b2) {
    const int t = blockIdx.x * blockDim.x + threadIdx.x;
    const int nu_1 = d_nu[0], nu_2 = d_nu[1], nu_g = d_nu[2], nu_r = d_nu[3];
    float ng2 = 0.0f, nr2 = 0.0f;

    if (t < MRv) {
        if (t < nu_r) {
            int v = d_sr[t];
            float p0, p1, p2; softmax3(Cr[3*v], Cr[3*v+1], Cr[3*v+2], p0, p1, p2);
            d_pr[t] = make_float4(p0, p1, p2, br[v]);
            nr2 = d_wr[t] * (p0*p0 + p1*p1 + p2*p2);
        }
    } else if (t < MRv + MGv) {
        int j = t - MRv;
        if (j < nu_g) {
            int v = d_sg[j];
            float p0, p1, p2; softmax3(Cg[3*v], Cg[3*v+1], Cg[3*v+2], p0, p1, p2);
            d_pg[j] = make_float4(p0, p1, p2, bg[v]);
            ng2 = d_wg[j] * (p0*p0 + p1*p1 + p2*p2);
        }
    } else if (t < MRv + MGv + M1v) {
        int i = t - MRv - MGv;
        if (i < nu_1) {
            int v = d_s1[i];
            float p0, p1, p2; softmax3(C1[3*v], C1[3*v+1], C1[3*v+2], p0, p1, p2);
            float q0 = p0*Ai[0] + p1*Ai[3] + p2*Ai[6];
            float q1 = p0*Ai[1] + p1*Ai[4] + p2*Ai[7];
            float q2 = p0*Ai[2] + p1*Ai[5] + p2*Ai[8];
            d_q1[i] = make_float4(q0, q1, q2, b1[v]);
        }
    } else if (t < MRv + MGv + M1v + M2v) {
        int i = t - MRv - MGv - M1v;
        if (i < nu_2) {
            int v = d_s2[i];
            float p0, p1, p2; softmax3(C2[3*v], C2[3*v+1], C2[3*v+2], p0, p1, p2);
            float q0 = p0*Ai[0] + p1*Ai[3] + p2*Ai[6];
            float q1 = p0*Ai[1] + p1*Ai[4] + p2*Ai[7];
            float q2 = p0*Ai[2] + p1*Ai[5] + p2*Ai[8];
            d_q2[i] = make_float4(q0, q1, q2, b2[v]);
        }
    }

    __shared__ float rg[256], rr[256];
    const int tid = threadIdx.x;
    rg[tid] = ng2; rr[tid] = nr2;
    __syncthreads();
    for (int s = 128; s > 0; s >>= 1) {
        if (tid < s) { rg[tid] += rg[tid + s]; rr[tid] += rr[tid + s]; }
        __syncthreads();
    }
    if (tid == 0) {
        if (rg[0] != 0.0f) atomicAdd(&d_acc[3], (double)rg[0]);
        if (rr[0] != 0.0f) atomicAdd(&d_acc[4], (double)rr[0]);
    }
}

// ---------------- fused loss kernel: loss3 blocks, then loss2, then loss1 ----------------
__global__ void loss_kernel(const float* __restrict__ G, const float* __restrict__ R,
                            const float* __restrict__ A) {
    __shared__ float4 sq[64];
    __shared__ int    soff[64];
    __shared__ float  sw[64];
    __shared__ float  red[256];
    const int tid = threadIdx.x;
    int b = blockIdx.x;

    if (b < NB3) {
        // ---- loss3: S += w_i w_j * pg_i . pr_j * A[sg_i, sr_j] ----
        const int bx = b % GX3, by = b / GX3;
        const int nu_i = d_nu[2], nu_j = d_nu[3];
        const int i0 = by * 64;
        if (i0 >= nu_i || bx * 256 >= nu_j) return;
        if (tid < 64) {
            int i = i0 + tid;
            if (i < nu_i) {
                float4 p = d_pg[i]; float w = d_wg[i];
                sq[tid] = make_float4(p.x * w, p.y * w, p.z * w, 0.0f);
                soff[tid] = d_sg[i] * RD;
            }
        }
        __syncthreads();
        const int j = bx * 256 + tid;
        float contrib = 0.0f;
        if (j < nu_j) {
            float4 pj = d_pr[j]; int col = d_sr[j]; float wj = d_wr[j];
            float a0 = 0.0f, a1 = 0.0f, a2 = 0.0f;
            const int ilim = min(64, nu_i - i0);
            #pragma unroll 4
            for (int i = 0; i < ilim; i++) {
                float a  = __ldg(A + soff[i] + col);
                float4 g = sq[i];
                a0 = fmaf(a, g.x, a0);
                a1 = fmaf(a, g.y, a1);
                a2 = fmaf(a, g.z, a2);
            }
            contrib = (a0 * pj.x + a1 * pj.y + a2 * pj.z) * wj;
        }
        red[tid] = contrib;
        __syncthreads();
        for (int s = 128; s > 0; s >>= 1) {
            if (tid < s) red[tid] += red[tid + s];
            __syncthreads();
        }
        if (tid == 0) atomicAdd(&d_acc[2], (double)red[0]);
        return;
    }
    b -= NB3;

    // ---- weighted squared-residual losses ----
    const float* X; int ld, TI, bx, by, nu_i, nu_j, accIdx;
    const int *si, *sj; const float *wiA, *wjA; const float4 *qA, *pA;
    if (b < NB2) {           // loss2 over R
        X = R; ld = RD; TI = 64; bx = b % GX2; by = b / GX2;
        nu_i = d_nu[1]; nu_j = d_nu[3]; accIdx = 1;
        si = d_s2; wiA = d_w2; qA = d_q2; sj = d_sr; wjA = d_wr; pA = d_pr;
    } else {                 // loss1 over G
        b -= NB2;
        X = G; ld = GD; TI = 32; bx = b % GX1; by = b / GX1;
        nu_i = d_nu[0]; nu_j = d_nu[2]; accIdx = 0;
        si = d_s1; wiA = d_w1; qA = d_q1; sj = d_sg; wjA = d_wg; pA = d_pg;
    }
    const int i0 = by * TI;
    if (i0 >= nu_i || bx * 256 >= nu_j) return;
    if (tid < TI) {
        int i = i0 + tid;
        if (i < nu_i) { sq[tid] = qA[i]; soff[tid] = si[i] * ld; sw[tid] = wiA[i]; }
    }
    __syncthreads();
    const int j = bx * 256 + tid;
    float acc = 0.0f;
    if (j < nu_j) {
        float4 pj = pA[j]; int col = sj[j]; float wj = wjA[j];
        const int ilim = min(TI, nu_i - i0);
        #pragma unroll 4
        for (int i = 0; i < ilim; i++) {
            float4 qi = sq[i];
            float g = __ldg(X + soff[i] + col);
            float r = g - fmaf(qi.x, pj.x, fmaf(qi.y, pj.y, qi.z * pj.z)) - pj.w - qi.w;
            acc = fmaf(sw[i] * r, r, acc);      // weight by row multiplicity
        }
        acc *= wj;                              // weight by col multiplicity
    }
    red[tid] = acc;
    __syncthreads();
    for (int s = 128; s > 0; s >>= 1) {
        if (tid < s) red[tid] += red[tid + s];
        __syncthreads();
    }
    if (tid == 0) atomicAdd(&d_acc[accIdx], (double)red[0]);
}

// ---------------- finalize ----------------
__global__ void finalize_kernel(float* __restrict__ out) {
    double l1 = d_acc[0] / (double)((long long)M1v * MGv);
    double l2 = d_acc[1] / (double)((long long)M2v * MRv);
    double l3 = -d_acc[2] / (sqrt(d_acc[3]) * sqrt(d_acc[4]));
    double t1 = 1000.0 * l1;
    double t2 = 1000.0 * l2;
    double t3 = 100.0  * l3;
    out[0] = (float)(t1 + t2 + t3);
    out[1] = (float)t1;
    out[2] = (float)t2;
    out[3] = (float)t3;
    out[4] = 0.0f;   // ALPHA[3] == 0 -> exactly 0
}

// ---------------- launch ----------------
extern "C" void kernel_launch(void* const* d_in, const int* in_sizes, int n_in,
                              void* d_out, int out_size) {
    const float* G  = (const float*)d_in[0];
    const float* R  = (const float*)d_in[1];
    const float* A  = (const float*)d_in[2];
    const float* C1 = (const float*)d_in[3];
    const float* C2 = (const float*)d_in[4];
    const float* Cg = (const float*)d_in[5];
    const float* Cr = (const float*)d_in[6];
    const float* Ai = (const float*)d_in[7];
    const float* bg = (const float*)d_in[8];
    const float* br = (const float*)d_in[9];
    const float* b1 = (const float*)d_in[10];
    const float* b2 = (const float*)d_in[11];
    const int* m1 = (const int*)d_in[12];
    const int* m2 = (const int*)d_in[13];
    const int* mg = (const int*)d_in[14];
    const int* mr = (const int*)d_in[15];
    float* out = (float*)d_out;

    // largest histogram (R_DIM = 20000 ints = 80 KB) exceeds default 48 KB
    cudaFuncSetAttribute(sort_kernel,
                         cudaFuncAttributeMaxDynamicSharedMemorySize,
                         RD * (int)sizeof(int));

    sort_kernel<<<4, 1024, RD * sizeof(int)>>>(m1, m2, mg, mr);

    {
        int total = MRv + MGv + M1v + M2v;          // 10800
        prep_kernel<<<(total + 255) / 256, 256>>>(C1, C2, Cg, Cr, Ai, bg, br, b1, b2);
    }

    loss_kernel<<<NBT, 256>>>(G, R, A);

    finalize_kernel<<<1, 1>>>(out);
}